// round 14
// baseline (speedup 1.0000x reference)
#include <cuda_runtime.h>

// LBP (radius=1, 8 points, skimage 'default') over NCHW fp32, zero boundary.
// Batched-load regime: each thread loads its ENTIRE 10-row x 6-col window
// (30 LDGs) up front, then computes all 8 output rows as one FP burst.
// Per-warp MLP ~10-30 hides DRAM latency within the warp, so occupancy can
// drop: __launch_bounds__(224, 3) gives ptxas 97 regs to keep loads hoisted.
// Math: R12 threshold-folded diagonals; code sum tree-reassociated (exact).

template <bool GUARD>
__device__ __forceinline__ void lbp_strip(
    const float* __restrict__ ip, float* __restrict__ op,
    int x0, int y0, bool has_left, bool has_right)
{
    constexpr int H = 224, W = 224;

    // Bilinear weights (float32 of double products, as jax produces).
    const double Fd = 0.70710678;
    const double Gd = 1.0 - Fd;
    const float WD = (float)(Fd * Fd);
    const float WE = (float)(Fd * Gd);
    const float WC = (float)(Gd * Gd);
    const float KC = 1.0f - WC;          // threshold: v' >= KC*c

    // Full window: rows y0-1 .. y0+8, [left, v0..v3, right] each.
    float buf[10][6];

    const float* base = ip + y0 * W + x0;

    // Batched front load: 10 x (1 LDG.128 + 2 LDG.32), no compute between.
    #pragma unroll
    for (int k = 0; k < 10; k++) {
        float* b = buf[k];
        const int rel = k - 1;
        if (!GUARD || (unsigned)(y0 + rel) < (unsigned)H) {
            const float* rp = base + rel * W;
            const float4 v = *reinterpret_cast<const float4*>(rp);
            b[0] = has_left  ? __ldg(rp - 1) : 0.0f;
            b[1] = v.x; b[2] = v.y; b[3] = v.z; b[4] = v.w;
            b[5] = has_right ? __ldg(rp + 4) : 0.0f;
        } else {
            b[0] = b[1] = b[2] = b[3] = b[4] = b[5] = 0.0f;
        }
    }

    float* wp = op + y0 * W + x0;

    #pragma unroll
    for (int r = 0; r < 8; r++) {
        const float* N = buf[r];
        const float* C = buf[r + 1];
        const float* S = buf[r + 2];

        float4 res;
        float* resp = &res.x;

        #pragma unroll
        for (int i = 0; i < 4; i++) {
            const float nw = N[i], nn = N[i + 1], ne = N[i + 2];
            const float ww = C[i], c  = C[i + 1], ee = C[i + 2];
            const float sw = S[i], ss = S[i + 1], se = S[i + 2];

            // Shared WE-products; center term folded into threshold cc.
            const float tn = WE * nn;
            const float te = WE * ee;
            const float tw = WE * ww;
            const float ts = WE * ss;
            const float cc = KC * c;

            const float v1 = (tn + WD * ne) + te;   // up-right
            const float v3 = (WD * nw + tn) + tw;   // up-left
            const float v5 = (tw + WD * sw) + ts;   // down-left
            const float v7 = (te + ts) + WD * se;   // down-right

            // Tree-reassociated bit sum (powers of two: exact in fp32).
            const float b0 = (ee >= c)  ?   1.0f : 0.0f;
            const float b1 = (v1 >= cc) ?   2.0f : 0.0f;
            const float b2 = (nn >= c)  ?   4.0f : 0.0f;
            const float b3 = (v3 >= cc) ?   8.0f : 0.0f;
            const float b4 = (ww >= c)  ?  16.0f : 0.0f;
            const float b5 = (v5 >= cc) ?  32.0f : 0.0f;
            const float b6 = (ss >= c)  ?  64.0f : 0.0f;
            const float b7 = (v7 >= cc) ? 128.0f : 0.0f;
            resp[i] = ((b0 + b1) + (b2 + b3)) + ((b4 + b5) + (b6 + b7));
        }

        __stcs(reinterpret_cast<float4*>(wp), res);  // streaming store
        wp += W;
    }
}

__global__ __launch_bounds__(224, 3) void lbp_kernel(
    const float* __restrict__ in, float* __restrict__ out)
{
    constexpr int H = 224, W = 224;

    const int plane = blockIdx.z;
    const float* ip = in + (size_t)plane * (H * W);
    float*       op = out + (size_t)plane * (H * W);

    const int tx = threadIdx.x;                        // column group 0..55
    const int x0 = tx * 4;
    const int by = blockIdx.y;
    const int y0 = by * 32 + threadIdx.y * 8;          // strip row base

    const bool has_left  = (tx > 0);
    const bool has_right = (tx < 55);

    if (by >= 1 && by <= 5) {
        // Interior: rows y0-1 .. y0+8 all within [0, 223] -> no bounds checks.
        lbp_strip<false>(ip, op, x0, y0, has_left, has_right);
    } else {
        lbp_strip<true>(ip, op, x0, y0, has_left, has_right);
    }
}

extern "C" void kernel_launch(void* const* d_in, const int* in_sizes, int n_in,
                              void* d_out, int out_size)
{
    const float* x = (const float*)d_in[0];
    float* out = (float*)d_out;

    constexpr int H = 224, W = 224;
    const int planes = out_size / (H * W);   // B*C = 1024

    dim3 block(56, 4, 1);                    // 224 threads = 7 warps
    dim3 grid(1, 7, planes);
    lbp_kernel<<<grid, block>>>(x, out);
}

// round 15
// speedup vs baseline: 1.0552x; 1.0552x over previous
#include <cuda_runtime.h>

// LBP (radius=1, 8 points, skimage 'default') over NCHW fp32, zero boundary.
// Best-measured config (R10/R12): 4x8 strip/thread, block (56,4),
// grid (1,7,planes), 4-slot rolling buffer prefetch d2, guard-free interior
// y-blocks, threshold-folded diagonal math, predicated-FADD bit accumulation.
// New: zero-page edge pointers — image-edge threads point their left/right
// scalar-load pointers into a zero-filled __device__ array instead of
// selecting values per row. All row loads become 3 unconditional LDGs:
// no per-row predication, no FSELs.

// Zero page: indexed as zp + W + k*W + {-1,+4} for k in [-1, 8] -> needs
// [0, 10*W+4); 12*W floats is comfortably enough. Never written -> all zeros.
__device__ float g_zero_page[12 * 224];

template <bool GUARD>
__device__ __forceinline__ void lbp_strip(
    const float* __restrict__ ip, float* __restrict__ op,
    int x0, int y0, bool has_left, bool has_right)
{
    constexpr int H = 224, W = 224;

    // Bilinear weights (float32 of double products, as jax produces).
    const double Fd = 0.70710678;
    const double Gd = 1.0 - Fd;
    const float WD = (float)(Fd * Fd);
    const float WE = (float)(Fd * Gd);
    const float WC = (float)(Gd * Gd);
    const float KC = 1.0f - WC;          // threshold: v' >= KC*c

    const float* base = ip + y0 * W + x0;

    // Edge pointers: real neighbors, or the zero page (offset so that
    // +k*W stays in bounds for k = -1..8).
    const float* zp     = g_zero_page + W;
    const float* leftp  = has_left  ? (base - 1) : zp;
    const float* rightp = has_right ? (base + 4) : zp;

    // buf[(k+1)&3] holds relative row k, [left, v0..v3, right].
    float buf[4][6];

    auto load_row = [&](float* b, int k) {
        if (!GUARD || (unsigned)(y0 + k) < (unsigned)H) {
            const float4 v = *reinterpret_cast<const float4*>(base + k * W);
            b[0] = __ldg(leftp + k * W);
            b[1] = v.x; b[2] = v.y; b[3] = v.z; b[4] = v.w;
            b[5] = __ldg(rightp + k * W);
        } else {
            b[0] = b[1] = b[2] = b[3] = b[4] = b[5] = 0.0f;
        }
    };

    // Prologue: rows -1, 0, 1.
    load_row(buf[0], -1);
    load_row(buf[1], 0);
    load_row(buf[2], 1);

    float* wp = op + y0 * W + x0;

    #pragma unroll
    for (int r = 0; r < 8; r++) {
        // Prefetch row r+2 (first consumed by compute r+1).
        if (r < 7)
            load_row(buf[(r + 3) & 3], r + 2);

        const float* N = buf[r & 3];
        const float* C = buf[(r + 1) & 3];
        const float* S = buf[(r + 2) & 3];

        float4 res;
        float* resp = &res.x;

        #pragma unroll
        for (int i = 0; i < 4; i++) {
            const float nw = N[i], nn = N[i + 1], ne = N[i + 2];
            const float ww = C[i], c  = C[i + 1], ee = C[i + 2];
            const float sw = S[i], ss = S[i + 1], se = S[i + 2];

            // Shared WE-products; center term folded into threshold cc.
            const float tn = WE * nn;
            const float te = WE * ee;
            const float tw = WE * ww;
            const float ts = WE * ss;
            const float cc = KC * c;

            const float v1 = (tn + WD * ne) + te;   // up-right
            const float v3 = (WD * nw + tn) + tw;   // up-left
            const float v5 = (tw + WD * sw) + ts;   // down-left
            const float v7 = (te + ts) + WD * se;   // down-right

            float code = (ee >= c) ? 1.0f : 0.0f;   // p=0: east
            if (v1 >= cc) code += 2.0f;             // p=1
            if (nn >= c)  code += 4.0f;             // p=2: north
            if (v3 >= cc) code += 8.0f;             // p=3
            if (ww >= c)  code += 16.0f;            // p=4: west
            if (v5 >= cc) code += 32.0f;            // p=5
            if (ss >= c)  code += 64.0f;            // p=6: south
            if (v7 >= cc) code += 128.0f;           // p=7
            resp[i] = code;
        }

        __stcs(reinterpret_cast<float4*>(wp), res);  // streaming store
        wp += W;
    }
}

__global__ __launch_bounds__(224, 6) void lbp_kernel(
    const float* __restrict__ in, float* __restrict__ out)
{
    constexpr int H = 224, W = 224;

    const int plane = blockIdx.z;
    const float* ip = in + (size_t)plane * (H * W);
    float*       op = out + (size_t)plane * (H * W);

    const int tx = threadIdx.x;                        // column group 0..55
    const int x0 = tx * 4;
    const int by = blockIdx.y;
    const int y0 = by * 32 + threadIdx.y * 8;          // strip row base

    const bool has_left  = (tx > 0);
    const bool has_right = (tx < 55);

    if (by >= 1 && by <= 5) {
        // Interior: rows y0-1 .. y0+8 all within [0, 223] -> no bounds checks.
        lbp_strip<false>(ip, op, x0, y0, has_left, has_right);
    } else {
        lbp_strip<true>(ip, op, x0, y0, has_left, has_right);
    }
}

extern "C" void kernel_launch(void* const* d_in, const int* in_sizes, int n_in,
                              void* d_out, int out_size)
{
    const float* x = (const float*)d_in[0];
    float* out = (float*)d_out;

    constexpr int H = 224, W = 224;
    const int planes = out_size / (H * W);   // B*C = 1024

    dim3 block(56, 4, 1);                    // 224 threads = 7 warps
    dim3 grid(1, 7, planes);
    lbp_kernel<<<grid, block>>>(x, out);
}

// round 16
// speedup vs baseline: 1.1466x; 1.0867x over previous
#include <cuda_runtime.h>

// LBP (radius=1, 8 points, skimage 'default') over NCHW fp32, zero boundary.
// R12 core (best measured, tied 69.7us): 4x8 strip/thread, rolling 4-slot
// buffer prefetch d2, guard-free interior y-blocks, threshold-folded math,
// predicated-FADD bit accumulation.
// New (single variable): block (28,4)=112 threads instead of (56,4)=224,
// grid (2,7,planes). Per-thread code identical, regs stay ~40, but blocks/SM
// rises 6 -> 14 (49 warps, 76.5% theoretical occ) WITHOUT any register cap —
// retests R11's occupancy theory with the ptxas reg-clamp confound removed.

template <bool GUARD>
__device__ __forceinline__ void lbp_strip(
    const float* __restrict__ ip, float* __restrict__ op,
    int x0, int y0, bool has_left, bool has_right)
{
    constexpr int H = 224, W = 224;

    // Bilinear weights (float32 of double products, as jax produces).
    const double Fd = 0.70710678;
    const double Gd = 1.0 - Fd;
    const float WD = (float)(Fd * Fd);
    const float WE = (float)(Fd * Gd);
    const float WC = (float)(Gd * Gd);
    const float KC = 1.0f - WC;          // threshold: v' >= KC*c

    // buf[(k+1)&3] holds relative row k, [left, v0..v3, right].
    float buf[4][6];

    const float* base = ip + y0 * W + x0;

    auto load_row = [&](float* b, int k) {
        if (!GUARD || (unsigned)(y0 + k) < (unsigned)H) {
            const float* rp = base + k * W;
            const float4 v = *reinterpret_cast<const float4*>(rp);
            b[0] = has_left  ? __ldg(rp - 1) : 0.0f;
            b[1] = v.x; b[2] = v.y; b[3] = v.z; b[4] = v.w;
            b[5] = has_right ? __ldg(rp + 4) : 0.0f;
        } else {
            b[0] = b[1] = b[2] = b[3] = b[4] = b[5] = 0.0f;
        }
    };

    // Prologue: rows -1, 0, 1.
    load_row(buf[0], -1);
    load_row(buf[1], 0);
    load_row(buf[2], 1);

    float* wp = op + y0 * W + x0;

    #pragma unroll
    for (int r = 0; r < 8; r++) {
        // Prefetch row r+2 (first consumed by compute r+1).
        if (r < 7)
            load_row(buf[(r + 3) & 3], r + 2);

        const float* N = buf[r & 3];
        const float* C = buf[(r + 1) & 3];
        const float* S = buf[(r + 2) & 3];

        float4 res;
        float* resp = &res.x;

        #pragma unroll
        for (int i = 0; i < 4; i++) {
            const float nw = N[i], nn = N[i + 1], ne = N[i + 2];
            const float ww = C[i], c  = C[i + 1], ee = C[i + 2];
            const float sw = S[i], ss = S[i + 1], se = S[i + 2];

            // Shared WE-products; center term folded into threshold cc.
            const float tn = WE * nn;
            const float te = WE * ee;
            const float tw = WE * ww;
            const float ts = WE * ss;
            const float cc = KC * c;

            const float v1 = (tn + WD * ne) + te;   // up-right
            const float v3 = (WD * nw + tn) + tw;   // up-left
            const float v5 = (tw + WD * sw) + ts;   // down-left
            const float v7 = (te + ts) + WD * se;   // down-right

            float code = (ee >= c) ? 1.0f : 0.0f;   // p=0: east
            if (v1 >= cc) code += 2.0f;             // p=1
            if (nn >= c)  code += 4.0f;             // p=2: north
            if (v3 >= cc) code += 8.0f;             // p=3
            if (ww >= c)  code += 16.0f;            // p=4: west
            if (v5 >= cc) code += 32.0f;            // p=5
            if (ss >= c)  code += 64.0f;            // p=6: south
            if (v7 >= cc) code += 128.0f;           // p=7
            resp[i] = code;
        }

        __stcs(reinterpret_cast<float4*>(wp), res);  // streaming store
        wp += W;
    }
}

__global__ __launch_bounds__(112) void lbp_kernel(
    const float* __restrict__ in, float* __restrict__ out)
{
    constexpr int H = 224, W = 224;

    const int plane = blockIdx.z;
    const float* ip = in + (size_t)plane * (H * W);
    float*       op = out + (size_t)plane * (H * W);

    const int cg = blockIdx.x * 28 + threadIdx.x;      // column group 0..55
    const int x0 = cg * 4;
    const int by = blockIdx.y;
    const int y0 = by * 32 + threadIdx.y * 8;          // strip row base

    const bool has_left  = (cg > 0);
    const bool has_right = (cg < 55);

    if (by >= 1 && by <= 5) {
        // Interior: rows y0-1 .. y0+8 all within [0, 223] -> no bounds checks.
        lbp_strip<false>(ip, op, x0, y0, has_left, has_right);
    } else {
        lbp_strip<true>(ip, op, x0, y0, has_left, has_right);
    }
}

extern "C" void kernel_launch(void* const* d_in, const int* in_sizes, int n_in,
                              void* d_out, int out_size)
{
    const float* x = (const float*)d_in[0];
    float* out = (float*)d_out;

    constexpr int H = 224, W = 224;
    const int planes = out_size / (H * W);   // B*C = 1024

    dim3 block(28, 4, 1);                    // 112 threads
    dim3 grid(2, 7, planes);
    lbp_kernel<<<grid, block>>>(x, out);
}

// round 17
// speedup vs baseline: 1.1574x; 1.0095x over previous
#include <cuda_runtime.h>

// LBP (radius=1, 8 points, skimage 'default') over NCHW fp32, zero boundary.
// R16 core (best measured, 68.3us): 4x8 strip/thread, rolling 4-slot buffer
// prefetch d2, threshold-folded diagonal math, predicated-FADD accumulation.
// New (single variable): flattened 1D task mapping with 64-thread blocks
// (2 FULL warps) — removes R16's half-empty warp per block (12.5% dead
// lanes) and shrinks scheduling granularity further.
// Tasks: 56 col-groups x 28 y-strips x planes; 1,605,632 = 25,088 x 64.

template <bool GUARD>
__device__ __forceinline__ void lbp_strip(
    const float* __restrict__ ip, float* __restrict__ op,
    int x0, int y0, bool has_left, bool has_right)
{
    constexpr int H = 224, W = 224;

    // Bilinear weights (float32 of double products, as jax produces).
    const double Fd = 0.70710678;
    const double Gd = 1.0 - Fd;
    const float WD = (float)(Fd * Fd);
    const float WE = (float)(Fd * Gd);
    const float WC = (float)(Gd * Gd);
    const float KC = 1.0f - WC;          // threshold: v' >= KC*c

    // buf[(k+1)&3] holds relative row k, [left, v0..v3, right].
    float buf[4][6];

    const float* base = ip + y0 * W + x0;

    auto load_row = [&](float* b, int k) {
        if (!GUARD || (unsigned)(y0 + k) < (unsigned)H) {
            const float* rp = base + k * W;
            const float4 v = *reinterpret_cast<const float4*>(rp);
            b[0] = has_left  ? __ldg(rp - 1) : 0.0f;
            b[1] = v.x; b[2] = v.y; b[3] = v.z; b[4] = v.w;
            b[5] = has_right ? __ldg(rp + 4) : 0.0f;
        } else {
            b[0] = b[1] = b[2] = b[3] = b[4] = b[5] = 0.0f;
        }
    };

    // Prologue: rows -1, 0, 1.
    load_row(buf[0], -1);
    load_row(buf[1], 0);
    load_row(buf[2], 1);

    float* wp = op + y0 * W + x0;

    #pragma unroll
    for (int r = 0; r < 8; r++) {
        // Prefetch row r+2 (first consumed by compute r+1).
        if (r < 7)
            load_row(buf[(r + 3) & 3], r + 2);

        const float* N = buf[r & 3];
        const float* C = buf[(r + 1) & 3];
        const float* S = buf[(r + 2) & 3];

        float4 res;
        float* resp = &res.x;

        #pragma unroll
        for (int i = 0; i < 4; i++) {
            const float nw = N[i], nn = N[i + 1], ne = N[i + 2];
            const float ww = C[i], c  = C[i + 1], ee = C[i + 2];
            const float sw = S[i], ss = S[i + 1], se = S[i + 2];

            // Shared WE-products; center term folded into threshold cc.
            const float tn = WE * nn;
            const float te = WE * ee;
            const float tw = WE * ww;
            const float ts = WE * ss;
            const float cc = KC * c;

            const float v1 = (tn + WD * ne) + te;   // up-right
            const float v3 = (WD * nw + tn) + tw;   // up-left
            const float v5 = (tw + WD * sw) + ts;   // down-left
            const float v7 = (te + ts) + WD * se;   // down-right

            float code = (ee >= c) ? 1.0f : 0.0f;   // p=0: east
            if (v1 >= cc) code += 2.0f;             // p=1
            if (nn >= c)  code += 4.0f;             // p=2: north
            if (v3 >= cc) code += 8.0f;             // p=3
            if (ww >= c)  code += 16.0f;            // p=4: west
            if (v5 >= cc) code += 32.0f;            // p=5
            if (ss >= c)  code += 64.0f;            // p=6: south
            if (v7 >= cc) code += 128.0f;           // p=7
            resp[i] = code;
        }

        __stcs(reinterpret_cast<float4*>(wp), res);  // streaming store
        wp += W;
    }
}

__global__ __launch_bounds__(64) void lbp_kernel(
    const float* __restrict__ in, float* __restrict__ out)
{
    constexpr int H = 224, W = 224;

    // Flattened task id -> (cg, sy, plane). 56 cgs x 28 strips per plane.
    const int task  = blockIdx.x * 64 + threadIdx.x;
    const int cg    = task % 56;                 // column group 0..55
    const int rest  = task / 56;
    const int sy    = rest % 28;                 // y-strip 0..27
    const int plane = rest / 28;

    const float* ip = in + (size_t)plane * (H * W);
    float*       op = out + (size_t)plane * (H * W);

    const int x0 = cg * 4;
    const int y0 = sy * 8;

    const bool has_left  = (cg > 0);
    const bool has_right = (cg < 55);

    if (sy >= 1 && sy <= 26) {
        // Interior: rows y0-1 .. y0+8 all within [0, 223] -> no bounds checks.
        lbp_strip<false>(ip, op, x0, y0, has_left, has_right);
    } else {
        lbp_strip<true>(ip, op, x0, y0, has_left, has_right);
    }
}

extern "C" void kernel_launch(void* const* d_in, const int* in_sizes, int n_in,
                              void* d_out, int out_size)
{
    const float* x = (const float*)d_in[0];
    float* out = (float*)d_out;

    constexpr int H = 224, W = 224;
    const int planes = out_size / (H * W);           // B*C = 1024
    const int tasks  = planes * 56 * 28;             // 1,605,632
    const int blocks = tasks / 64;                   // 25,088

    lbp_kernel<<<blocks, 64>>>(x, out);
}